// round 2
// baseline (speedup 1.0000x reference)
#include <cuda_runtime.h>
#include <cuda_bf16.h>
#include <math_constants.h>

// Problem shape: B=4, H=16, L=2048, D=64 (fp32)
#define BHN 64
#define LL  2048
#define DD  64

static const size_t CTX_ELEMS = (size_t)BHN * LL * DD;          // 8,388,608
static const size_t ATT_ELEMS = (size_t)BHN * LL * (size_t)LL;  // 268,435,456

// Scratch: per-(bh, n-tile) partial row sums of exp(S), and per-row inverse sums.
__device__ float g_partial[BHN * 16 * LL];   // 8 MB
__device__ float g_inv[BHN * LL];            // 512 KB

typedef unsigned long long ull;

__device__ __forceinline__ ull dup2(float x) {
    ull r; asm("mov.b64 %0, {%1, %1};" : "=l"(r) : "f"(x)); return r;
}
__device__ __forceinline__ ull pack2(float x, float y) {
    ull r; asm("mov.b64 %0, {%1, %2};" : "=l"(r) : "f"(x), "f"(y)); return r;
}
__device__ __forceinline__ void ffma2(ull& d, ull a, ull b) {
    asm("fma.rn.f32x2 %0, %1, %2, %0;" : "+l"(d) : "l"(a), "l"(b));
}
__device__ __forceinline__ void unpack2(ull v, float& lo, float& hi) {
    asm("mov.b64 {%0, %1}, %2;" : "=f"(lo), "=f"(hi) : "l"(v));
}

// ---------------------------------------------------------------------------
// K1: E[bh,i,j] = exp( sum_d Q[bh,i,d]*K[bh,j,d] ), plus per-CTA row sums.
// 128x128 tile, 256 threads, 8x8 per thread via packed f32x2 FMA.
// smem: Qs[64][128] + Ks[64][128] (transposed, [d][row]) = 64 KB dynamic.
// ---------------------------------------------------------------------------
__global__ __launch_bounds__(256, 2) void qk_exp_kernel(const float* __restrict__ Q,
                                                        const float* __restrict__ K,
                                                        float* __restrict__ E) {
    extern __shared__ float sm[];
    float* Qs = sm;              // [64][128]
    float* Ks = sm + 64 * 128;   // [64][128]

    const int bh = blockIdx.z;
    const int tileM = blockIdx.y * 128;
    const int tileN = blockIdx.x * 128;
    const float* Qb = Q + ((size_t)bh * LL + tileM) * DD;
    const float* Kb = K + ((size_t)bh * LL + tileN) * DD;
    const int tid = threadIdx.x;

    // Load 128x64 Q and K tiles, transposed into [d][row].
#pragma unroll
    for (int i = 0; i < 8; i++) {
        int lin = tid + i * 256;            // 0..2047 (float4 units)
        int row = lin >> 4;                 // 0..127
        int d4 = (lin & 15) << 2;           // 0..60
        float4 q = *(const float4*)(Qb + (size_t)row * DD + d4);
        Qs[(d4 + 0) * 128 + row] = q.x; Qs[(d4 + 1) * 128 + row] = q.y;
        Qs[(d4 + 2) * 128 + row] = q.z; Qs[(d4 + 3) * 128 + row] = q.w;
        float4 k = *(const float4*)(Kb + (size_t)row * DD + d4);
        Ks[(d4 + 0) * 128 + row] = k.x; Ks[(d4 + 1) * 128 + row] = k.y;
        Ks[(d4 + 2) * 128 + row] = k.z; Ks[(d4 + 3) * 128 + row] = k.w;
    }
    __syncthreads();

    const int tm = (tid >> 4) << 3;   // 0..120 (row group)
    const int tn = (tid & 15) << 3;   // 0..120 (col group)

    ull acc[8][4];
#pragma unroll
    for (int i = 0; i < 8; i++)
#pragma unroll
        for (int j = 0; j < 4; j++) acc[i][j] = 0ull;

#pragma unroll 16
    for (int dk = 0; dk < 64; dk++) {
        float4 a0 = *(const float4*)(Qs + dk * 128 + tm);
        float4 a1 = *(const float4*)(Qs + dk * 128 + tm + 4);
        float4 b0 = *(const float4*)(Ks + dk * 128 + tn);
        float4 b1 = *(const float4*)(Ks + dk * 128 + tn + 4);
        ull b2[4] = {pack2(b0.x, b0.y), pack2(b0.z, b0.w),
                     pack2(b1.x, b1.y), pack2(b1.z, b1.w)};
        ull a2[8] = {dup2(a0.x), dup2(a0.y), dup2(a0.z), dup2(a0.w),
                     dup2(a1.x), dup2(a1.y), dup2(a1.z), dup2(a1.w)};
#pragma unroll
        for (int i = 0; i < 8; i++)
#pragma unroll
            for (int j = 0; j < 4; j++) ffma2(acc[i][j], a2[i], b2[j]);
    }

    // Epilogue: exp, row partial sums (deterministic shfl over 16 lanes), store.
    float rs[8];
#pragma unroll
    for (int i = 0; i < 8; i++) {
        float e0, e1, e2, e3, e4, e5, e6, e7;
        unpack2(acc[i][0], e0, e1); unpack2(acc[i][1], e2, e3);
        unpack2(acc[i][2], e4, e5); unpack2(acc[i][3], e6, e7);
        e0 = __expf(e0); e1 = __expf(e1); e2 = __expf(e2); e3 = __expf(e3);
        e4 = __expf(e4); e5 = __expf(e5); e6 = __expf(e6); e7 = __expf(e7);
        rs[i] = ((e0 + e1) + (e2 + e3)) + ((e4 + e5) + (e6 + e7));
        size_t off = ((size_t)bh * LL + tileM + tm + i) * LL + tileN + tn;
        *(float4*)(E + off)     = make_float4(e0, e1, e2, e3);
        *(float4*)(E + off + 4) = make_float4(e4, e5, e6, e7);
    }
#pragma unroll
    for (int i = 0; i < 8; i++) {
#pragma unroll
        for (int o = 8; o > 0; o >>= 1)
            rs[i] += __shfl_xor_sync(0xffffffffu, rs[i], o);
    }
    if ((tid & 15) == 0) {
        float* pp = g_partial + ((size_t)bh * 16 + blockIdx.x) * LL + tileM + tm;
#pragma unroll
        for (int i = 0; i < 8; i++) pp[i] = rs[i];
    }
}

// ---------------------------------------------------------------------------
// K2: inv[bh,row] = 1 / sum over 16 n-tile partials.
// ---------------------------------------------------------------------------
__global__ __launch_bounds__(256) void reduce_kernel() {
    int t = blockIdx.x * 256 + threadIdx.x;       // 0..131071
    int bh = t >> 11, row = t & 2047;
    const float* p = g_partial + (size_t)bh * 16 * LL + row;
    float s = 0.f;
#pragma unroll
    for (int n = 0; n < 16; n++) s += p[n * LL];
    g_inv[t] = 1.0f / s;
}

// ---------------------------------------------------------------------------
// K3: normalize attn in place AND compute O = P @ V.
// 128x64 tile (full D), 128 threads, 8x8 per thread, K-chunks of 64.
// smem: Es[64][132] + Vs[64][64] + invS[128] = 50.7 KB dynamic.
// ---------------------------------------------------------------------------
#define PV_SMEM_FLOATS (64 * 132 + 64 * 64 + 128)
__global__ __launch_bounds__(128, 4) void pv_kernel(float* __restrict__ E,
                                                    const float* __restrict__ V,
                                                    float* __restrict__ O) {
    extern __shared__ float sm[];
    float* Es = sm;                    // [64][132] (transposed [j][row], padded)
    float* Vs = sm + 64 * 132;         // [64][64]
    float* invS = Vs + 64 * 64;        // [128]

    const int bh = blockIdx.y;
    const int tileM = blockIdx.x * 128;
    float* Eb = E + ((size_t)bh * LL + tileM) * LL;
    const float* Vb = V + (size_t)bh * LL * DD;
    float* Ob = O + ((size_t)bh * LL + tileM) * DD;
    const int tid = threadIdx.x;

    invS[tid] = g_inv[bh * LL + tileM + tid];
    __syncthreads();

    const int tm = (tid >> 3) << 3;   // 0..120 (row group)
    const int tn = (tid & 7) << 3;    // 0..56  (col group)

    ull acc[8][4];
#pragma unroll
    for (int i = 0; i < 8; i++)
#pragma unroll
        for (int j = 0; j < 4; j++) acc[i][j] = 0ull;

    for (int k0 = 0; k0 < LL; k0 += 64) {
        // Load E chunk (128 rows x 64 j), normalize, write back, STS transposed.
#pragma unroll
        for (int i = 0; i < 16; i++) {
            int lin = tid + i * 128;          // 0..2047 (float4 units)
            int row = lin >> 4;               // 0..127
            int j4 = (lin & 15) << 2;         // 0..60
            float* gp = Eb + (size_t)row * LL + k0 + j4;
            float4 e = *(const float4*)gp;
            float iv = invS[row];
            float4 p = make_float4(e.x * iv, e.y * iv, e.z * iv, e.w * iv);
            *(float4*)gp = p;
            Es[(j4 + 0) * 132 + row] = p.x; Es[(j4 + 1) * 132 + row] = p.y;
            Es[(j4 + 2) * 132 + row] = p.z; Es[(j4 + 3) * 132 + row] = p.w;
        }
        // Load V chunk (64 j x 64 d), natural layout.
#pragma unroll
        for (int i = 0; i < 8; i++) {
            int lin = tid + i * 128;          // 0..1023
            int j = lin >> 4;                 // 0..63
            int d4 = (lin & 15) << 2;         // 0..60
            *(float4*)(Vs + j * 64 + d4) =
                *(const float4*)(Vb + (size_t)(k0 + j) * DD + d4);
        }
        __syncthreads();

#pragma unroll 16
        for (int dk = 0; dk < 64; dk++) {
            float4 a0 = *(const float4*)(Es + dk * 132 + tm);
            float4 a1 = *(const float4*)(Es + dk * 132 + tm + 4);
            float4 b0 = *(const float4*)(Vs + dk * 64 + tn);
            float4 b1 = *(const float4*)(Vs + dk * 64 + tn + 4);
            ull b2[4] = {pack2(b0.x, b0.y), pack2(b0.z, b0.w),
                         pack2(b1.x, b1.y), pack2(b1.z, b1.w)};
            ull a2[8] = {dup2(a0.x), dup2(a0.y), dup2(a0.z), dup2(a0.w),
                         dup2(a1.x), dup2(a1.y), dup2(a1.z), dup2(a1.w)};
#pragma unroll
            for (int i = 0; i < 8; i++)
#pragma unroll
                for (int j = 0; j < 4; j++) ffma2(acc[i][j], a2[i], b2[j]);
        }
        __syncthreads();
    }

#pragma unroll
    for (int i = 0; i < 8; i++) {
        float c0, c1, c2, c3, c4, c5, c6, c7;
        unpack2(acc[i][0], c0, c1); unpack2(acc[i][1], c2, c3);
        unpack2(acc[i][2], c4, c5); unpack2(acc[i][3], c6, c7);
        float* op = Ob + (size_t)(tm + i) * DD + tn;
        *(float4*)(op)     = make_float4(c0, c1, c2, c3);
        *(float4*)(op + 4) = make_float4(c4, c5, c6, c7);
    }
}

// ---------------------------------------------------------------------------
// attn-only path helper: normalize E in place (no PV).
// ---------------------------------------------------------------------------
__global__ __launch_bounds__(256) void normalize_kernel(float* __restrict__ E) {
    size_t idx = (size_t)blockIdx.x * 256 + threadIdx.x;   // float4 units
    size_t row = idx >> 9;                                 // 512 float4 per row
    float iv = g_inv[row];
    float4* p = ((float4*)E) + idx;
    float4 v = *p;
    v.x *= iv; v.y *= iv; v.z *= iv; v.w *= iv;
    *p = v;
}

// ---------------------------------------------------------------------------
// ctx-only fallback: fused per-row attention (rarely used branch).
// ---------------------------------------------------------------------------
__global__ __launch_bounds__(256) void fused_ctx_kernel(const float* __restrict__ Q,
                                                        const float* __restrict__ K,
                                                        const float* __restrict__ V,
                                                        float* __restrict__ O) {
    __shared__ float q[DD];
    __shared__ float s[LL];
    __shared__ float wred[8];
    __shared__ float bcast;

    const int bh = blockIdx.y;
    const int qi = blockIdx.x;
    const float* Qb = Q + ((size_t)bh * LL + qi) * DD;
    const float* Kb = K + (size_t)bh * LL * DD;
    const float* Vb = V + (size_t)bh * LL * DD;
    float* Ob = O + ((size_t)bh * LL + qi) * DD;

    const int tid = threadIdx.x;
    const int warp = tid >> 5, lane = tid & 31;
    if (tid < DD) q[tid] = Qb[tid];
    __syncthreads();

    float m = -CUDART_INF_F;
    for (int j = tid; j < LL; j += 256) {
        float d = 0.f;
#pragma unroll
        for (int d0 = 0; d0 < DD; d0++) d = fmaf(q[d0], Kb[(size_t)j * DD + d0], d);
        s[j] = d;
        m = fmaxf(m, d);
    }
#pragma unroll
    for (int o = 16; o > 0; o >>= 1) m = fmaxf(m, __shfl_xor_sync(0xffffffffu, m, o));
    if (lane == 0) wred[warp] = m;
    __syncthreads();
    if (warp == 0) {
        float x = (lane < 8) ? wred[lane] : -CUDART_INF_F;
#pragma unroll
        for (int o = 4; o > 0; o >>= 1) x = fmaxf(x, __shfl_xor_sync(0xffffffffu, x, o));
        if (lane == 0) bcast = x;
    }
    __syncthreads();
    m = bcast;

    float ssum = 0.f;
    for (int j = tid; j < LL; j += 256) {
        float e = __expf(s[j] - m);
        s[j] = e;
        ssum += e;
    }
#pragma unroll
    for (int o = 16; o > 0; o >>= 1) ssum += __shfl_xor_sync(0xffffffffu, ssum, o);
    __syncthreads();
    if (lane == 0) wred[warp] = ssum;
    __syncthreads();
    if (warp == 0) {
        float x = (lane < 8) ? wred[lane] : 0.f;
#pragma unroll
        for (int o = 4; o > 0; o >>= 1) x += __shfl_xor_sync(0xffffffffu, x, o);
        if (lane == 0) bcast = 1.f / x;
    }
    __syncthreads();
    const float inv = bcast;

    if (tid < DD) {
        float a = 0.f;
        for (int j = 0; j < LL; j++) a = fmaf(s[j], Vb[(size_t)j * DD + tid], a);
        Ob[tid] = a * inv;
    }
}

// ---------------------------------------------------------------------------
extern "C" void kernel_launch(void* const* d_in, const int* in_sizes, int n_in,
                              void* d_out, int out_size) {
    const float* Q = (const float*)d_in[0];
    const float* K = (const float*)d_in[1];
    const float* V = (const float*)d_in[2];
    float* out = (float*)d_out;

    cudaFuncSetAttribute(qk_exp_kernel, cudaFuncAttributeMaxDynamicSharedMemorySize,
                         64 * 128 * 2 * sizeof(float));
    cudaFuncSetAttribute(pv_kernel, cudaFuncAttributeMaxDynamicSharedMemorySize,
                         PV_SMEM_FLOATS * sizeof(float));

    if ((size_t)out_size >= CTX_ELEMS + ATT_ELEMS) {
        float* ctx = out;
        float* att = out + CTX_ELEMS;
        qk_exp_kernel<<<dim3(16, 16, BHN), 256, 64 * 128 * 2 * sizeof(float)>>>(Q, K, att);
        reduce_kernel<<<512, 256>>>();
        pv_kernel<<<dim3(16, BHN), 128, PV_SMEM_FLOATS * sizeof(float)>>>(att, V, ctx);
    } else if ((size_t)out_size == ATT_ELEMS) {
        qk_exp_kernel<<<dim3(16, 16, BHN), 256, 64 * 128 * 2 * sizeof(float)>>>(Q, K, out);
        reduce_kernel<<<512, 256>>>();
        normalize_kernel<<<262144, 256>>>(out);
    } else {
        fused_ctx_kernel<<<dim3(LL, BHN), 256>>>(Q, K, V, out);
    }
}